// round 14
// baseline (speedup 1.0000x reference)
#include <cuda_runtime.h>
#include <cuda_bf16.h>
#include <cstdint>

#define B_ROWS     524288
#define D_DIM      64
#define TROWS      128                       // rows per stage tile
#define NTILES     (B_ROWS / TROWS)          // 4096
#define GRID       148
#define THREADS    288                       // 8 consumer warps + 1 producer warp
#define NSTAGE     6
#define STG_BYTES  (TROWS * D_DIM * 4)       // 32768
#define STG_FLOATS (TROWS * D_DIM)           // 8192
#define SMEM_BYTES (NSTAGE * STG_BYTES + 9000 * 2)   // 214608

__device__ float        g_part[GRID];
__device__ unsigned int g_count = 0;

__device__ __forceinline__ void mbar_wait(uint32_t mbar, uint32_t parity) {
    uint32_t done;
    asm volatile(
        "{\n\t.reg .pred p;\n\t"
        "mbarrier.try_wait.parity.acquire.cta.shared::cta.b64 p, [%1], %2;\n\t"
        "selp.b32 %0, 1, 0, p;\n\t}"
        : "=r"(done) : "r"(mbar), "r"(parity) : "memory");
    if (!done) {
        asm volatile(
            "{\n\t.reg .pred P1;\n\t"
            "WL_%=:\n\t"
            "mbarrier.try_wait.parity.acquire.cta.shared::cta.b64 P1, [%0], %1, 0x989680;\n\t"
            "@P1 bra.uni WD_%=;\n\t"
            "bra.uni WL_%=;\n\t"
            "WD_%=:\n\t}"
            :: "r"(mbar), "r"(parity) : "memory");
    }
}

__device__ __forceinline__ void bulk_copy(uint32_t dst_smem, const void* src,
                                          uint32_t bytes, uint32_t mbar) {
    asm volatile("mbarrier.arrive.expect_tx.shared.b64 _, [%0], %1;"
                 :: "r"(mbar), "r"(bytes) : "memory");
    asm volatile(
        "cp.async.bulk.shared::cluster.global.mbarrier::complete_tx::bytes "
        "[%0], [%1], %2, [%3];"
        :: "r"(dst_smem), "l"(src), "r"(bytes), "r"(mbar) : "memory");
}

__global__ void __launch_bounds__(THREADS, 1) mcl_main(
    const float* __restrict__ x,
    const int*   __restrict__ labels,   // int32 on device
    const float* __restrict__ lin_w,
    const float* __restrict__ lin_b,
    const float* __restrict__ linear_p,
    const float* __restrict__ bias_p,
    const float* __restrict__ centers,
    float*       __restrict__ out)
{
    extern __shared__ __align__(128) float smem[];
    float*         sx   = smem;                                   // 6 stages
    __nv_bfloat16* stab = (__nv_bfloat16*)(smem + NSTAGE * STG_FLOATS);
    __shared__ __align__(16) float sw[D_DIM];
    __shared__ __align__(8) unsigned long long mb_full[NSTAGE];
    __shared__ __align__(8) unsigned long long mb_empty[NSTAGE];
    __shared__ float warp_acc[THREADS / 32];
    __shared__ bool  s_last;

    const int tid = threadIdx.x;
    const int bid = blockIdx.x;
    const int wid = tid >> 5;
    const uint32_t smem_u32  = (uint32_t)__cvta_generic_to_shared(smem);
    const uint32_t full_u32  = (uint32_t)__cvta_generic_to_shared(mb_full);
    const uint32_t empty_u32 = (uint32_t)__cvta_generic_to_shared(mb_empty);

    // number of tiles this CTA owns
    const int n = (NTILES - 1 - bid) / GRID + 1;

    if (tid == 0) {
        #pragma unroll
        for (int i = 0; i < NSTAGE; i++) {
            asm volatile("mbarrier.init.shared.b64 [%0], 1;"
                         :: "r"(full_u32 + 8 * i) : "memory");
            asm volatile("mbarrier.init.shared.b64 [%0], 4;"
                         :: "r"(empty_u32 + 8 * i) : "memory");
        }
    }
    // tables + weights (all 288 threads help)
    for (int i = tid; i < 3000; i += THREADS) {
        stab[i]        = __float2bfloat16(__ldg(linear_p + i));
        stab[3000 + i] = __float2bfloat16(__ldg(bias_p   + i));
        stab[6000 + i] = __float2bfloat16(__ldg(centers  + i));
    }
    if (tid < D_DIM / 4)
        ((float4*)sw)[tid] = ((const float4*)lin_w)[tid];
    const float lb = __ldg(lin_b);
    __syncthreads();

    float acc = 0.f;

    if (tid == 256) {
        // ---------------- producer: free-running TMA ring ----------------
        for (int k = 0; k < n; k++) {
            const int s = k % NSTAGE;
            const int f = k / NSTAGE;
            if (f > 0)
                mbar_wait(empty_u32 + 8 * s, (uint32_t)((f - 1) & 1));
            const float* src = x + ((size_t)bid + (size_t)k * GRID) * STG_FLOATS;
            bulk_copy(smem_u32 + s * STG_BYTES, src, STG_BYTES, full_u32 + 8 * s);
        }
    } else if (wid < 8) {
        // ---------------- consumers: 2 groups alternate stages -----------
        const int g      = wid >> 2;        // group 0: warps 0-3, group 1: 4-7
        const int wg_tid = tid & 127;       // row within tile
        const float4* swq = (const float4*)sw;

        for (int k = g; k < n; k += 2) {
            const int s = k % NSTAGE;
            const size_t row_g = ((size_t)bid + (size_t)k * GRID) * TROWS + wg_tid;
            int lab = __ldg(labels + row_g);
            lab = min(max(lab, 0), 999);

            mbar_wait(full_u32 + 8 * s, (uint32_t)((k / NSTAGE) & 1));

            const float4* xr = (const float4*)(sx + s * STG_FLOATS) + wg_tid * 16;
            float m = 0.f, ssum = 0.f, q = 0.f;
            #pragma unroll
            for (int j = 0; j < 16; j++) {
                const int qi = (j + wg_tid) & 15;   // conflict-free rotation
                float4 v = xr[qi];
                float4 w = swq[qi];
                m = fmaf(v.x, w.x, m); m = fmaf(v.y, w.y, m);
                m = fmaf(v.z, w.z, m); m = fmaf(v.w, w.w, m);
                ssum += (v.x + v.y) + (v.z + v.w);
                q = fmaf(v.x, v.x, q); q = fmaf(v.y, v.y, q);
                q = fmaf(v.z, v.z, q); q = fmaf(v.w, v.w, q);
            }

            __syncwarp();
            if ((tid & 31) == 0)
                asm volatile("mbarrier.arrive.shared.b64 _, [%0];"
                             :: "r"(empty_u32 + 8 * s) : "memory");

            m += lb;
            const int l3 = lab * 3;
            const float A0 = __bfloat162float(stab[l3 + 0]);
            const float A1 = __bfloat162float(stab[l3 + 1]);
            const float A2 = __bfloat162float(stab[l3 + 2]);
            const float B0 = __bfloat162float(stab[3000 + l3 + 0]);
            const float B1 = __bfloat162float(stab[3000 + l3 + 1]);
            const float B2 = __bfloat162float(stab[3000 + l3 + 2]);
            const float C0 = __bfloat162float(stab[6000 + l3 + 0]);
            const float C1 = __bfloat162float(stab[6000 + l3 + 1]);
            const float C2 = __bfloat162float(stab[6000 + l3 + 2]);

            const float l0 = fmaf(m, A0, B0);
            const float l1 = fmaf(m, A1, B1);
            const float l2 = fmaf(m, A2, B2);
            const float mx = fmaxf(l0, fmaxf(l1, l2));
            const float e0 = __expf(l0 - mx);
            const float e1 = __expf(l1 - mx);
            const float e2 = __expf(l2 - mx);
            const float inv = 1.f / (e0 + e1 + e2);

            const float t0 = C0 * fmaf(64.f, C0, -2.f * ssum);
            const float t1 = C1 * fmaf(64.f, C1, -2.f * ssum);
            const float t2 = C2 * fmaf(64.f, C2, -2.f * ssum);
            acc += q + inv * (e0 * t0 + e1 * t1 + e2 * t2);
        }
    }

    // ---------------- CTA reduction + fused finalize ----------------
    #pragma unroll
    for (int o = 16; o > 0; o >>= 1)
        acc += __shfl_xor_sync(0xffffffffu, acc, o);
    if ((tid & 31) == 0)
        warp_acc[wid] = acc;
    __syncthreads();
    if (tid == 0) {
        float t = 0.f;
        #pragma unroll
        for (int i = 0; i < THREADS / 32; i++) t += warp_acc[i];
        g_part[bid] = t;
        __threadfence();
        unsigned int old = atomicAdd(&g_count, 1u);
        s_last = (old == GRID - 1);
    }
    __syncthreads();

    if (s_last && tid < 32) {
        double t = 0.0;
        for (int i = tid; i < GRID; i += 32)
            t += (double)g_part[i];
        #pragma unroll
        for (int o = 16; o > 0; o >>= 1)
            t += __shfl_xor_sync(0xffffffffu, t, o);
        if (tid == 0) {
            out[0] = (float)(t / (double)B_ROWS);
            g_count = 0;   // rearm for next graph replay
        }
    }
}

extern "C" void kernel_launch(void* const* d_in, const int* in_sizes, int n_in,
                              void* d_out, int out_size)
{
    const float* x        = (const float*)d_in[0];
    const int*   labels   = (const int*)d_in[1];
    const float* lin_w    = (const float*)d_in[2];
    const float* lin_b    = (const float*)d_in[3];
    const float* linear_p = (const float*)d_in[4];
    const float* bias_p   = (const float*)d_in[5];
    const float* centers  = (const float*)d_in[6];

    cudaFuncSetAttribute(mcl_main,
                         cudaFuncAttributeMaxDynamicSharedMemorySize, SMEM_BYTES);
    mcl_main<<<GRID, THREADS, SMEM_BYTES>>>(x, labels, lin_w, lin_b,
                                            linear_p, bias_p, centers,
                                            (float*)d_out);
}

// round 15
// speedup vs baseline: 1.0674x; 1.0674x over previous
#include <cuda_runtime.h>
#include <cstdint>

#define B_ROWS   524288
#define D_DIM    64
#define THREADS  512
#define GRID     296                          // 148 SMs * 2 CTAs
#define NGROUPS  (B_ROWS / 8)                 // 65536 row-groups (8 rows each)
#define NWARPS   (GRID * THREADS / 32)        // 4736

__device__ float        g_part[GRID];
__device__ unsigned int g_count = 0;          // reset by last block every call

__global__ void __launch_bounds__(THREADS, 2) mcl_main(
    const float* __restrict__ x,
    const int*   __restrict__ labels,   // int32 on device
    const float* __restrict__ lin_w,
    const float* __restrict__ lin_b,
    const float* __restrict__ linear_p,
    const float* __restrict__ bias_p,
    const float* __restrict__ centers,
    float*       __restrict__ out)
{
    __shared__ __align__(16) float stab[9000];   // fp32: A | B | C
    __shared__ __align__(16) float sw[D_DIM];
    __shared__ float warp_acc[THREADS / 32];
    __shared__ bool  s_last;

    const int tid  = threadIdx.x;
    const int bid  = blockIdx.x;
    const int lane = tid & 31;
    const int wid  = tid >> 5;
    const int gwid = bid * (THREADS / 32) + wid;   // global warp id
    const int h    = lane >> 4;                    // half-warp
    const int jl   = lane & 15;

    for (int i = tid; i < 3000; i += THREADS) {
        stab[i]        = __ldg(linear_p + i);
        stab[3000 + i] = __ldg(bias_p   + i);
        stab[6000 + i] = __ldg(centers  + i);
    }
    if (tid < D_DIM / 4)
        ((float4*)sw)[tid] = ((const float4*)lin_w)[tid];
    const float lb = __ldg(lin_b);
    __syncthreads();

    const float4  wq = ((const float4*)sw)[jl];    // same quad for all 4 loads
    const float4* xq = (const float4*)x;
    const bool epi   = (jl < 4);                   // 8 epilogue lanes per warp
    float acc = 0.f;

    for (int g = gwid; g < NGROUPS; g += NWARPS) {
        const int qbase = g * 128;

        // 4 perfectly lane-contiguous LDG.128 (4 lines each — minimum wavefronts)
        const float4 v0 = __ldg(xq + qbase + lane);
        const float4 v1 = __ldg(xq + qbase + lane + 32);
        const float4 v2 = __ldg(xq + qbase + lane + 64);
        const float4 v3 = __ldg(xq + qbase + lane + 96);

        // label prefetch for this lane's epilogue row: g*8 + 2*jl + h
        int lab = 0;
        if (epi)
            lab = min(max(__ldg(labels + (g * 8 + 2 * jl + h)), 0), 999);

        // per-j partials (each j is a different row: 2j + h)
        float m0 = v0.x * wq.x; m0 = fmaf(v0.y, wq.y, m0);
        m0 = fmaf(v0.z, wq.z, m0); m0 = fmaf(v0.w, wq.w, m0);
        float m1 = v1.x * wq.x; m1 = fmaf(v1.y, wq.y, m1);
        m1 = fmaf(v1.z, wq.z, m1); m1 = fmaf(v1.w, wq.w, m1);
        float m2 = v2.x * wq.x; m2 = fmaf(v2.y, wq.y, m2);
        m2 = fmaf(v2.z, wq.z, m2); m2 = fmaf(v2.w, wq.w, m2);
        float m3 = v3.x * wq.x; m3 = fmaf(v3.y, wq.y, m3);
        m3 = fmaf(v3.z, wq.z, m3); m3 = fmaf(v3.w, wq.w, m3);

        float s0 = (v0.x + v0.y) + (v0.z + v0.w);
        float s1 = (v1.x + v1.y) + (v1.z + v1.w);
        float s2 = (v2.x + v2.y) + (v2.z + v2.w);
        float s3 = (v3.x + v3.y) + (v3.z + v3.w);

        float q0 = v0.x * v0.x; q0 = fmaf(v0.y, v0.y, q0);
        q0 = fmaf(v0.z, v0.z, q0); q0 = fmaf(v0.w, v0.w, q0);
        float q1 = v1.x * v1.x; q1 = fmaf(v1.y, v1.y, q1);
        q1 = fmaf(v1.z, v1.z, q1); q1 = fmaf(v1.w, v1.w, q1);
        float q2 = v2.x * v2.x; q2 = fmaf(v2.y, v2.y, q2);
        q2 = fmaf(v2.z, v2.z, q2); q2 = fmaf(v2.w, v2.w, q2);
        float q3 = v3.x * v3.x; q3 = fmaf(v3.y, v3.y, q3);
        q3 = fmaf(v3.z, v3.z, q3); q3 = fmaf(v3.w, v3.w, q3);

        // butterfly over each 16-lane half (xor<16 keeps halves independent)
        #pragma unroll
        for (int o = 8; o > 0; o >>= 1) {
            m0 += __shfl_xor_sync(0xffffffffu, m0, o);
            m1 += __shfl_xor_sync(0xffffffffu, m1, o);
            m2 += __shfl_xor_sync(0xffffffffu, m2, o);
            m3 += __shfl_xor_sync(0xffffffffu, m3, o);
            s0 += __shfl_xor_sync(0xffffffffu, s0, o);
            s1 += __shfl_xor_sync(0xffffffffu, s1, o);
            s2 += __shfl_xor_sync(0xffffffffu, s2, o);
            s3 += __shfl_xor_sync(0xffffffffu, s3, o);
            q0 += __shfl_xor_sync(0xffffffffu, q0, o);
            q1 += __shfl_xor_sync(0xffffffffu, q1, o);
            q2 += __shfl_xor_sync(0xffffffffu, q2, o);
            q3 += __shfl_xor_sync(0xffffffffu, q3, o);
        }

        if (epi) {
            // static slot select for this lane's row (jl in 0..3)
            float m = m0, s = s0, q = q0;
            if (jl == 1) { m = m1; s = s1; q = q1; }
            if (jl == 2) { m = m2; s = s2; q = q2; }
            if (jl == 3) { m = m3; s = s3; q = q3; }

            m += lb;
            const int l3 = lab * 3;
            const float A0 = stab[l3 + 0];
            const float A1 = stab[l3 + 1];
            const float A2 = stab[l3 + 2];
            const float B0 = stab[3000 + l3 + 0];
            const float B1 = stab[3000 + l3 + 1];
            const float B2 = stab[3000 + l3 + 2];
            const float C0 = stab[6000 + l3 + 0];
            const float C1 = stab[6000 + l3 + 1];
            const float C2 = stab[6000 + l3 + 2];

            const float l0 = fmaf(m, A0, B0);
            const float l1 = fmaf(m, A1, B1);
            const float l2 = fmaf(m, A2, B2);
            const float mx = fmaxf(l0, fmaxf(l1, l2));
            const float e0 = __expf(l0 - mx);
            const float e1 = __expf(l1 - mx);
            const float e2 = __expf(l2 - mx);
            const float inv = 1.f / (e0 + e1 + e2);

            const float t0 = C0 * fmaf(64.f, C0, -2.f * s);
            const float t1 = C1 * fmaf(64.f, C1, -2.f * s);
            const float t2 = C2 * fmaf(64.f, C2, -2.f * s);
            acc += q + inv * (e0 * t0 + e1 * t1 + e2 * t2);
        }
    }

    // block reduction
    #pragma unroll
    for (int o = 16; o > 0; o >>= 1)
        acc += __shfl_xor_sync(0xffffffffu, acc, o);
    if (lane == 0)
        warp_acc[wid] = acc;
    __syncthreads();
    if (tid == 0) {
        float t = 0.f;
        #pragma unroll
        for (int i = 0; i < THREADS / 32; i++) t += warp_acc[i];
        g_part[bid] = t;
        __threadfence();
        unsigned int old = atomicAdd(&g_count, 1u);
        s_last = (old == GRID - 1);
    }
    __syncthreads();

    // last block finalizes: fixed-order double reduction (deterministic)
    if (s_last && tid < 32) {
        double t = 0.0;
        for (int i = tid; i < GRID; i += 32)
            t += (double)g_part[i];
        #pragma unroll
        for (int o = 16; o > 0; o >>= 1)
            t += __shfl_xor_sync(0xffffffffu, t, o);
        if (tid == 0) {
            out[0] = (float)(t / (double)B_ROWS);
            g_count = 0;   // rearm for next graph replay
        }
    }
}

extern "C" void kernel_launch(void* const* d_in, const int* in_sizes, int n_in,
                              void* d_out, int out_size)
{
    const float* x        = (const float*)d_in[0];
    const int*   labels   = (const int*)d_in[1];
    const float* lin_w    = (const float*)d_in[2];
    const float* lin_b    = (const float*)d_in[3];
    const float* linear_p = (const float*)d_in[4];
    const float* bias_p   = (const float*)d_in[5];
    const float* centers  = (const float*)d_in[6];

    mcl_main<<<GRID, THREADS>>>(x, labels, lin_w, lin_b,
                                linear_p, bias_p, centers, (float*)d_out);
}